// round 8
// baseline (speedup 1.0000x reference)
#include <cuda_runtime.h>
#include <stdint.h>

#define GS 128            // grid dim
#define VX 132            // vol8 x-stride (padded from 129; 33 words)
#define VY 129
#define VZ 129
#define VTOT (VZ*VY*VX)   // 2,196,612 bytes

// Packed neighborhood volume: byte at (z,y,x) (z,y,x in [0,129))
// holds bits of grid[z-1+dz][y-1+dy][x-1+dx] (0 if OOB) at bit dz*4+dy*2+dx.
__device__ uint8_t  g_vol8[VTOT];
// Bitmask of grid: word (zz*128+yy)*4 + w has bit i = grid[zz][yy][32w+i] != 0.
__device__ uint32_t g_bits[GS*GS*4];

// ---- Kernel 1: pack binary grid into bitmask ----
__global__ void pack_bits_kernel(const float4* __restrict__ grid4) {
    int t = blockIdx.x * blockDim.x + threadIdx.x;   // 0 .. 524287
    float4 v = __ldcs(grid4 + t);
    unsigned nib = (v.x != 0.0f ? 1u : 0u)
                 | (v.y != 0.0f ? 2u : 0u)
                 | (v.z != 0.0f ? 4u : 0u)
                 | (v.w != 0.0f ? 8u : 0u);
    unsigned word = nib << (4 * (threadIdx.x & 7));
    word |= __shfl_xor_sync(0xffffffffu, word, 1);
    word |= __shfl_xor_sync(0xffffffffu, word, 2);
    word |= __shfl_xor_sync(0xffffffffu, word, 4);
    if ((threadIdx.x & 7) == 0) g_bits[t >> 3] = word;
}

// ---- Kernel 2: build vol8 from the bitmask ----
// Chunk c covers x_out = 32c..32c+31; chunk 4 writes only 1 word
// (x=128..131, 129-131 pad) to avoid spilling into the next row.
__global__ void build_vol8_kernel() {
    int id = blockIdx.x * blockDim.x + threadIdx.x;
    if (id >= VZ * VY * 5) return;
    int c = id % 5;
    int t = id / 5;
    int y = t % VY;
    int z = t / VY;
    int by = y - 1, bz = z - 1;

    uint64_t v[4];
#pragma unroll
    for (int dz = 0; dz < 2; ++dz) {
        int zz = bz + dz;
#pragma unroll
        for (int dy = 0; dy < 2; ++dy) {
            int yy = by + dy;
            uint32_t lo = 0, hi = 0;
            if (zz >= 0 && zz < GS && yy >= 0 && yy < GS) {
                const uint32_t* row = &g_bits[(zz * GS + yy) * 4];
                if (c > 0) lo = __ldg(&row[c - 1]);
                if (c < 4) hi = __ldg(&row[c]);
            }
            v[dz * 2 + dy] = ((uint64_t)hi << 32) | (uint64_t)lo;
        }
    }

    int nw = (c == 4) ? 1 : 8;
    uint32_t* dst = (uint32_t*)&g_vol8[(size_t)(z * VY + y) * VX + 32 * c];
#pragma unroll
    for (int w = 0; w < 8; ++w) {
        if (w >= nw) break;
        uint32_t acc = 0;
#pragma unroll
        for (int j = 0; j < 4; ++j) {
            int k = w * 4 + j;
            unsigned byte = 0;
#pragma unroll
            for (int e = 0; e < 4; ++e)
                byte |= (unsigned)((v[e] >> (31 + k)) & 3ull) << (2 * e);
            acc |= byte << (8 * j);
        }
        dst[w] = acc;
    }
}

// ---- Kernel 3: sample ----
__device__ __forceinline__ float sample_one(float x, float y, float z) {
    // ((x+1)*128-1)*0.5 == fma(x, 64, 63.5)
    float ix = fmaf(x, 64.0f, 63.5f);
    float iy = fmaf(y, 64.0f, 63.5f);
    float iz = fmaf(z, 64.0f, 63.5f);
    float fx = floorf(ix), fy = floorf(iy), fz = floorf(iz);
    float wx = ix - fx, wy = iy - fy, wz = iz - fz;
    int ix0 = (int)fx, iy0 = (int)fy, iz0 = (int)fz;
    // coords in [-1,1] guarantee base in [-1,127]; clamp the composite index
    // only (memory safety; value-neutral for in-range inputs).
    int idx = ((iz0 + 1) * VY + (iy0 + 1)) * VX + (ix0 + 1);
    idx = min(VTOT - 1, max(0, idx));
    unsigned b = (unsigned)__ldg(&g_vol8[idx]);

    float f0 = (float)( b       & 1u);
    float f1 = (float)((b >> 1) & 1u);
    float f2 = (float)((b >> 2) & 1u);
    float f3 = (float)((b >> 3) & 1u);
    float f4 = (float)((b >> 4) & 1u);
    float f5 = (float)((b >> 5) & 1u);
    float f6 = (float)((b >> 6) & 1u);
    float f7 = (float)((b >> 7) & 1u);

    float c00 = fmaf(wx, f1 - f0, f0);
    float c10 = fmaf(wx, f3 - f2, f2);
    float c01 = fmaf(wx, f5 - f4, f4);
    float c11 = fmaf(wx, f7 - f6, f6);
    float c0  = fmaf(wy, c10 - c00, c00);
    float c1  = fmaf(wy, c11 - c01, c01);
    return fmaf(wz, c1 - c0, c0);
}

// 8 points per thread as two pipelined 4-point tiles: all 6 coord loads
// issued up-front so tile B's coords are in flight while tile A's gathers
// execute -> the L1tex gather queue never drains on a coord stall.
__global__ void sample_kernel(const float4* __restrict__ coords4,
                              float4* __restrict__ out4, int n8) {
    int tid = blockIdx.x * blockDim.x + threadIdx.x;
    if (tid >= n8) return;
    const float4* p = coords4 + (size_t)tid * 6;
    float4 a0 = __ldcs(p + 0);
    float4 a1 = __ldcs(p + 1);
    float4 a2 = __ldcs(p + 2);
    float4 b0 = __ldcs(p + 3);
    float4 b1 = __ldcs(p + 4);
    float4 b2 = __ldcs(p + 5);

    float4 oA;
    oA.x = sample_one(a0.x, a0.y, a0.z);
    oA.y = sample_one(a0.w, a1.x, a1.y);
    oA.z = sample_one(a1.z, a1.w, a2.x);
    oA.w = sample_one(a2.y, a2.z, a2.w);
    __stcs(&out4[(size_t)tid * 2 + 0], oA);

    float4 oB;
    oB.x = sample_one(b0.x, b0.y, b0.z);
    oB.y = sample_one(b0.w, b1.x, b1.y);
    oB.z = sample_one(b1.z, b1.w, b2.x);
    oB.w = sample_one(b2.y, b2.z, b2.w);
    __stcs(&out4[(size_t)tid * 2 + 1], oB);
}

extern "C" void kernel_launch(void* const* d_in, const int* in_sizes, int n_in,
                              void* d_out, int out_size) {
    const float* grid   = (const float*)d_in[0];   // 128^3 floats
    const float* coords = (const float*)d_in[1];   // N*3 floats
    float* out = (float*)d_out;                    // N floats

    // 1) pack grid -> bitmask
    {
        int nthreads = GS * GS * GS / 4;           // 524,288
        pack_bits_kernel<<<nthreads / 256, 256>>>((const float4*)grid);
    }
    // 2) bitmask -> packed neighborhood volume
    {
        int total = VZ * VY * 5;                   // 83,205
        build_vol8_kernel<<<(total + 255) / 256, 256>>>();
    }
    // 3) sample (8 pts/thread, two pipelined 4-pt tiles)
    {
        int n  = in_sizes[1] / 3;                  // 8,388,608
        int n8 = n / 8;                            // 1,048,576
        sample_kernel<<<n8 / 256, 256>>>((const float4*)coords,
                                         (float4*)out, n8);
    }
}

// round 9
// speedup vs baseline: 1.1934x; 1.1934x over previous
#include <cuda_runtime.h>
#include <stdint.h>

#define GS 128            // grid dim
#define VX 132            // vol8 x-stride (padded from 129; 33 words)
#define VY 129
#define VZ 129
#define VTOT (VZ*VY*VX)   // 2,196,612 bytes

// Packed neighborhood volume: byte at (z,y,x) (z,y,x in [0,129))
// holds bits of grid[z-1+dz][y-1+dy][x-1+dx] (0 if OOB) at bit dz*4+dy*2+dx.
__device__ uint8_t g_vol8[VTOT];

// ---- Fused build: one block per vol8 z-plane ----
// Block z packs grid planes gz = z-1, z into a smem bitmask (rows gy = -1..128
// stored at r+1, OOB rows zero), then emits the full 129x129 vol8 plane.
__global__ void __launch_bounds__(1024)
fused_build_kernel(const float4* __restrict__ grid4) {
    int z = blockIdx.x;                 // 0..128
    // bits[p][r][w]: bit i of word w = grid[z-1+p][r-1][32w+i] (0 if OOB)
    __shared__ uint32_t bits[2][130][4];
    int tid = threadIdx.x;

    // zero (covers the OOB boundary rows 0 and 129)
    if (tid < 2 * 130 * 4) ((uint32_t*)bits)[tid] = 0;
    __syncthreads();

    // ---- pack: 2 planes x 128 rows x 32 float4 = 8192 tasks, 8 per thread ----
#pragma unroll
    for (int it = 0; it < 8; ++it) {
        int idx = it * 1024 + tid;
        int p   = idx >> 12;            // plane 0/1
        int rem = idx & 4095;
        int r   = rem >> 5;             // grid row 0..127
        int q   = rem & 31;             // float4 within row (= lane)
        int gz  = z - 1 + p;
        unsigned nib = 0;
        if (gz >= 0 && gz < GS) {
            float4 v = __ldg(&grid4[gz * 4096 + r * 32 + q]);
            nib = (v.x != 0.0f ? 1u : 0u)
                | (v.y != 0.0f ? 2u : 0u)
                | (v.z != 0.0f ? 4u : 0u)
                | (v.w != 0.0f ? 8u : 0u);
        }
        unsigned word = nib << (4 * (tid & 7));
        word |= __shfl_xor_sync(0xffffffffu, word, 1);
        word |= __shfl_xor_sync(0xffffffffu, word, 2);
        word |= __shfl_xor_sync(0xffffffffu, word, 4);
        if ((tid & 7) == 0) bits[p][r + 1][q >> 3] = word;
    }
    __syncthreads();

    // ---- emit: 129 rows x 5 chunks = 645 tasks ----
    // Chunk c covers x_out = 32c..32c+31; chunk 4 writes only 1 word
    // (x=128..131, 129-131 pad) to avoid spilling into the next row.
    if (tid < VY * 5) {
        int c  = tid % 5;
        int rl = tid / 5;               // vol8 y = rl (0..128)
        // v[e] (e = dz*2+dy): 64-bit window of bits covering x = 32(c-1)..32c+31
        uint64_t v[4];
#pragma unroll
        for (int dz = 0; dz < 2; ++dz) {
#pragma unroll
            for (int dy = 0; dy < 2; ++dy) {
                // grid row rl-1+dy -> smem row rl+dy (0..129)
                uint32_t lo = (c > 0) ? bits[dz][rl + dy][c - 1] : 0u;
                uint32_t hi = (c < 4) ? bits[dz][rl + dy][c]     : 0u;
                v[dz * 2 + dy] = ((uint64_t)hi << 32) | (uint64_t)lo;
            }
        }
        int nw = (c == 4) ? 1 : 8;
        uint32_t* dst = (uint32_t*)&g_vol8[(size_t)(z * VY + rl) * VX + 32 * c];
#pragma unroll
        for (int w = 0; w < 8; ++w) {
            if (w >= nw) break;
            uint32_t acc = 0;
#pragma unroll
            for (int j = 0; j < 4; ++j) {
                int k = w * 4 + j;
                unsigned byte = 0;
#pragma unroll
                for (int e = 0; e < 4; ++e)
                    byte |= (unsigned)((v[e] >> (31 + k)) & 3ull) << (2 * e);
                acc |= byte << (8 * j);
            }
            dst[w] = acc;
        }
    }
}

// ---- Sample kernel (R6 exact: interleaved, 4 pts/thread, ~30 regs) ----
__device__ __forceinline__ float sample_one(float x, float y, float z) {
    float ix = ((x + 1.0f) * 128.0f - 1.0f) * 0.5f;
    float iy = ((y + 1.0f) * 128.0f - 1.0f) * 0.5f;
    float iz = ((z + 1.0f) * 128.0f - 1.0f) * 0.5f;
    float fx = floorf(ix), fy = floorf(iy), fz = floorf(iz);
    float wx = ix - fx, wy = iy - fy, wz = iz - fz;
    int ix0 = (int)fx, iy0 = (int)fy, iz0 = (int)fz;
    // coords in [-1,1] -> base in [-1,127]; clamp only for memory safety
    ix0 = min(127, max(-1, ix0));
    iy0 = min(127, max(-1, iy0));
    iz0 = min(127, max(-1, iz0));
    int idx = ((iz0 + 1) * VY + (iy0 + 1)) * VX + (ix0 + 1);
    unsigned b = (unsigned)__ldg(&g_vol8[idx]);

    float f0 = (float)( b       & 1u);
    float f1 = (float)((b >> 1) & 1u);
    float f2 = (float)((b >> 2) & 1u);
    float f3 = (float)((b >> 3) & 1u);
    float f4 = (float)((b >> 4) & 1u);
    float f5 = (float)((b >> 5) & 1u);
    float f6 = (float)((b >> 6) & 1u);
    float f7 = (float)((b >> 7) & 1u);

    float c00 = fmaf(wx, f1 - f0, f0);
    float c10 = fmaf(wx, f3 - f2, f2);
    float c01 = fmaf(wx, f5 - f4, f4);
    float c11 = fmaf(wx, f7 - f6, f6);
    float c0  = fmaf(wy, c10 - c00, c00);
    float c1  = fmaf(wy, c11 - c01, c01);
    return fmaf(wz, c1 - c0, c0);
}

// coords/out use streaming hints (evict-first) so the 2.2MB vol8 table keeps
// L1 residency for the gathers.
__global__ void sample_kernel(const float4* __restrict__ coords4,
                              float4* __restrict__ out4, int n4) {
    int tid = blockIdx.x * blockDim.x + threadIdx.x;
    if (tid >= n4) return;
    float4 a = __ldcs(&coords4[(size_t)tid * 3 + 0]);
    float4 b = __ldcs(&coords4[(size_t)tid * 3 + 1]);
    float4 c = __ldcs(&coords4[(size_t)tid * 3 + 2]);

    float4 o;
    o.x = sample_one(a.x, a.y, a.z);
    o.y = sample_one(a.w, b.x, b.y);
    o.z = sample_one(b.z, b.w, c.x);
    o.w = sample_one(c.y, c.z, c.w);
    __stcs(&out4[tid], o);
}

extern "C" void kernel_launch(void* const* d_in, const int* in_sizes, int n_in,
                              void* d_out, int out_size) {
    const float* grid   = (const float*)d_in[0];   // 128^3 floats
    const float* coords = (const float*)d_in[1];   // N*3 floats
    float* out = (float*)d_out;                    // N floats

    // 1) fused build: grid -> packed neighborhood volume (one launch)
    fused_build_kernel<<<VZ, 1024>>>((const float4*)grid);

    // 2) sample
    {
        int n  = in_sizes[1] / 3;                  // 8,388,608
        int n4 = n / 4;                            // 2,097,152
        sample_kernel<<<n4 / 256, 256>>>((const float4*)coords,
                                         (float4*)out, n4);
    }
}